// round 1
// baseline (speedup 1.0000x reference)
#include <cuda_runtime.h>

#define Bb   8
#define Nn   4096
#define Mm   2048
#define DIN  256
#define DOUT 128

// Scratch (allocation-free rule: __device__ globals)
__device__ float g_Q [Bb*Mm*DOUT];        // [b][m][e]
__device__ float g_Kt[Bb*DOUT*Mm];        // [b][e][n]  (transposed K)
__device__ float g_V [Bb*Mm*DOUT];        // [b][m][e]

// ---------------------------------------------------------------------------
// Kernel 1: gather + Q/K/V projections.
// 128 threads, 32-row tile. smem: gS[32][256] (32KB) + Ws[64][128] (32KB).
// Thread (tx=tid%32 -> 4 cols, ty=tid/32 -> 8 rows): 8x4 register tile.
// ---------------------------------------------------------------------------
__global__ __launch_bounds__(128)
void proj_kernel(const float* __restrict__ Y, const int* __restrict__ idx,
                 const float* __restrict__ Wq, const float* __restrict__ bq,
                 const float* __restrict__ Wk, const float* __restrict__ bk,
                 const float* __restrict__ Wv, const float* __restrict__ bv)
{
    extern __shared__ float sm[];
    float* gS = sm;             // 32*256
    float* Ws = sm + 32*256;    // 64*128
    __shared__ int idxs[32];

    const int tid  = threadIdx.x;
    const int row0 = blockIdx.x * 32;
    const int b    = row0 / Mm;
    const int m0   = row0 % Mm;

    if (tid < 32) idxs[tid] = idx[b*Mm + m0 + tid];
    __syncthreads();

    // gather 32 rows x 256 floats (float4)
    for (int i = tid; i < 32*64; i += 128) {
        int r = i >> 6, c4 = i & 63;
        const float4* yp = reinterpret_cast<const float4*>(
            Y + ((size_t)b*Nn + idxs[r]) * DIN);
        reinterpret_cast<float4*>(gS + r*DIN)[c4] = yp[c4];
    }
    // (covered by the sync at the top of the first k-chunk)

    const int tx = tid & 31;
    const int ty = tid >> 5;
    const int c0 = tx * 4;

    const float* Wlist[3] = {Wq, Wk, Wv};
    const float* blist[3] = {bq, bk, bv};

    #pragma unroll 1
    for (int wsel = 0; wsel < 3; ++wsel) {
        const float* W = Wlist[wsel];
        float acc[8][4];
        {
            float b0v = blist[wsel][c0+0], b1v = blist[wsel][c0+1];
            float b2v = blist[wsel][c0+2], b3v = blist[wsel][c0+3];
            #pragma unroll
            for (int r = 0; r < 8; r++) {
                acc[r][0]=b0v; acc[r][1]=b1v; acc[r][2]=b2v; acc[r][3]=b3v;
            }
        }

        #pragma unroll 1
        for (int k0 = 0; k0 < DIN; k0 += 64) {
            __syncthreads();     // protects Ws reuse + (first iter) gather done
            for (int i = tid; i < 64*32; i += 128) {
                int kk = i >> 5, c4 = i & 31;
                reinterpret_cast<float4*>(Ws + kk*DOUT)[c4] =
                    reinterpret_cast<const float4*>(W + (size_t)(k0+kk)*DOUT)[c4];
            }
            __syncthreads();
            #pragma unroll 4
            for (int kk = 0; kk < 64; kk++) {
                float4 w4 = reinterpret_cast<float4*>(Ws + kk*DOUT)[tx];
                #pragma unroll
                for (int r = 0; r < 8; r++) {
                    float gv = gS[(ty*8+r)*DIN + k0 + kk];  // warp broadcast
                    acc[r][0] = fmaf(gv, w4.x, acc[r][0]);
                    acc[r][1] = fmaf(gv, w4.y, acc[r][1]);
                    acc[r][2] = fmaf(gv, w4.z, acc[r][2]);
                    acc[r][3] = fmaf(gv, w4.w, acc[r][3]);
                }
            }
        }

        if (wsel == 0) {
            #pragma unroll
            for (int r = 0; r < 8; r++) {
                int m = m0 + ty*8 + r;
                float4 v4 = make_float4(acc[r][0],acc[r][1],acc[r][2],acc[r][3]);
                reinterpret_cast<float4*>(g_Q + ((size_t)b*Mm + m)*DOUT)[tx] = v4;
            }
        } else if (wsel == 1) {
            // transposed store: g_Kt[b][e][n]
            #pragma unroll
            for (int r = 0; r < 8; r++) {
                int m = m0 + ty*8 + r;
                #pragma unroll
                for (int j = 0; j < 4; j++)
                    g_Kt[((size_t)b*DOUT + c0 + j)*Mm + m] = acc[r][j];
            }
        } else {
            #pragma unroll
            for (int r = 0; r < 8; r++) {
                int m = m0 + ty*8 + r;
                float4 v4 = make_float4(fmaxf(acc[r][0],0.f), fmaxf(acc[r][1],0.f),
                                        fmaxf(acc[r][2],0.f), fmaxf(acc[r][3],0.f));
                reinterpret_cast<float4*>(g_V + ((size_t)b*Mm + m)*DOUT)[tx] = v4;
            }
        }
    }
}

// ---------------------------------------------------------------------------
// Kernel 2: fused attention for 16 query rows of one batch.
// 256 threads. smem: S[16][2048] 128KB + Qs/AVs[16][128] 8KB + Ts[128][128] 64KB.
// Phase 1: S = Q Kt / 16 (chunks of 128 keys).
// Softmax in smem, att written to gmem.
// Phase 2: AV = S V (chunks of 128 value rows), then dual-l2norm epilogue.
// ---------------------------------------------------------------------------
__global__ __launch_bounds__(256, 1)
void attn_kernel(float* __restrict__ out, float* __restrict__ att)
{
    extern __shared__ float sm[];
    float* S  = sm;                   // 16*2048
    float* Qs = sm + 16*2048;         // 16*128, reused as AVs in epilogue
    float* Ts = Qs + 16*DOUT;         // 128*128 (K chunk / V chunk)

    const int tid = threadIdx.x;      // 256
    const int b   = blockIdx.y;
    const int m0  = blockIdx.x * 16;

    // load Q tile
    for (int i = tid; i < 16*32; i += 256) {
        int r = i >> 5, c4 = i & 31;
        reinterpret_cast<float4*>(Qs + r*DOUT)[c4] =
            reinterpret_cast<const float4*>(g_Q + ((size_t)b*Mm + m0 + r)*DOUT)[c4];
    }

    const int cg = tid & 63;          // 64 col-groups of 2 (contiguous per lane)
    const int rg = tid >> 6;          // 4 row-groups of 4 (constant within warp)
    const int c0 = cg * 2;

    // ---------------- phase 1: S = Q K^T * (1/16) ----------------
    #pragma unroll 1
    for (int n0 = 0; n0 < Mm; n0 += 128) {
        __syncthreads();
        // stage KsT[k][n] (128 x 128): gmem coalesced, smem conflict-free
        for (int i = tid; i < 128*32; i += 256) {
            int k = i >> 5, c4 = i & 31;
            reinterpret_cast<float4*>(Ts + k*128)[c4] =
                reinterpret_cast<const float4*>(
                    g_Kt + ((size_t)b*DOUT + k)*Mm + n0)[c4];
        }
        __syncthreads();
        float acc[4][2] = {};
        #pragma unroll 4
        for (int k = 0; k < DOUT; k++) {
            float2 k2 = reinterpret_cast<float2*>(Ts + k*128)[cg];
            #pragma unroll
            for (int i = 0; i < 4; i++) {
                float qv = Qs[(rg*4 + i)*DOUT + k];   // warp broadcast
                acc[i][0] = fmaf(qv, k2.x, acc[i][0]);
                acc[i][1] = fmaf(qv, k2.y, acc[i][1]);
            }
        }
        const float scale = 0.0625f;  // 1/sqrt(256)
        #pragma unroll
        for (int i = 0; i < 4; i++) {
            S[(rg*4+i)*Mm + n0 + c0    ] = acc[i][0] * scale;
            S[(rg*4+i)*Mm + n0 + c0 + 1] = acc[i][1] * scale;
        }
    }
    __syncthreads();

    // ---------------- softmax (warp w owns rows 2w, 2w+1) ----------------
    {
        const int w = tid >> 5, lane = tid & 31;
        #pragma unroll 1
        for (int rr = 0; rr < 2; rr++) {
            int r = w*2 + rr;
            float* Sr = S + r*Mm;
            float mx = -1e30f;
            for (int n = lane; n < Mm; n += 32) mx = fmaxf(mx, Sr[n]);
            #pragma unroll
            for (int o = 16; o > 0; o >>= 1)
                mx = fmaxf(mx, __shfl_xor_sync(0xffffffffu, mx, o));
            float sum = 0.f;
            for (int n = lane; n < Mm; n += 32) {
                float e = __expf(Sr[n] - mx);
                Sr[n] = e;
                sum += e;
            }
            #pragma unroll
            for (int o = 16; o > 0; o >>= 1)
                sum += __shfl_xor_sync(0xffffffffu, sum, o);
            float inv = 1.f / sum;
            float* arow = att + ((size_t)b*Mm + m0 + r)*Mm;
            for (int n = lane; n < Mm; n += 32) {
                float v = Sr[n] * inv;
                Sr[n] = v;
                arow[n] = v;
            }
        }
    }
    __syncthreads();

    // ---------------- phase 2: AV = S @ V ----------------
    float acc2[4][2] = {};
    #pragma unroll 1
    for (int n0 = 0; n0 < Mm; n0 += 128) {
        __syncthreads();
        for (int i = tid; i < 128*32; i += 256) {
            int n = i >> 5, c4 = i & 31;
            reinterpret_cast<float4*>(Ts + n*DOUT)[c4] =
                reinterpret_cast<const float4*>(
                    g_V + ((size_t)b*Mm + n0 + n)*DOUT)[c4];
        }
        __syncthreads();
        #pragma unroll 4
        for (int n = 0; n < 128; n++) {
            float2 v2 = reinterpret_cast<float2*>(Ts + n*DOUT)[cg];
            #pragma unroll
            for (int i = 0; i < 4; i++) {
                float s = S[(rg*4+i)*Mm + n0 + n];    // warp broadcast
                acc2[i][0] = fmaf(s, v2.x, acc2[i][0]);
                acc2[i][1] = fmaf(s, v2.y, acc2[i][1]);
            }
        }
    }
    __syncthreads();
    // park AV in Qs (Q no longer needed)
    #pragma unroll
    for (int i = 0; i < 4; i++) {
        Qs[(rg*4+i)*DOUT + c0    ] = acc2[i][0];
        Qs[(rg*4+i)*DOUT + c0 + 1] = acc2[i][1];
    }
    __syncthreads();

    // ---------------- epilogue: out = l2norm(V + l2norm(AV)) ----------------
    {
        const int w = tid >> 5, lane = tid & 31;
        #pragma unroll 1
        for (int rr = 0; rr < 2; rr++) {
            int r = w*2 + rr;
            float av[4], t[4];
            float ss = 0.f;
            #pragma unroll
            for (int j = 0; j < 4; j++) {
                av[j] = Qs[r*DOUT + lane + j*32];
                ss += av[j]*av[j];
            }
            #pragma unroll
            for (int o = 16; o > 0; o >>= 1)
                ss += __shfl_xor_sync(0xffffffffu, ss, o);
            float inv1 = rsqrtf(fmaxf(ss, 1e-12f));
            const float* vrow = g_V + ((size_t)b*Mm + m0 + r)*DOUT;
            float ss2 = 0.f;
            #pragma unroll
            for (int j = 0; j < 4; j++) {
                t[j] = vrow[lane + j*32] + av[j]*inv1;
                ss2 += t[j]*t[j];
            }
            #pragma unroll
            for (int o = 16; o > 0; o >>= 1)
                ss2 += __shfl_xor_sync(0xffffffffu, ss2, o);
            float inv2 = rsqrtf(fmaxf(ss2, 1e-12f));
            float* orow = out + ((size_t)b*Mm + m0 + r)*DOUT;
            #pragma unroll
            for (int j = 0; j < 4; j++)
                orow[lane + j*32] = t[j]*inv2;
        }
    }
}

// ---------------------------------------------------------------------------
extern "C" void kernel_launch(void* const* d_in, const int* in_sizes, int n_in,
                              void* d_out, int out_size)
{
    const float* Y   = (const float*)d_in[0];
    const int*   idx = (const int*)  d_in[1];
    const float* Wq  = (const float*)d_in[2];
    const float* bq  = (const float*)d_in[3];
    const float* Wk  = (const float*)d_in[4];
    const float* bk  = (const float*)d_in[5];
    const float* Wv  = (const float*)d_in[6];
    const float* bv  = (const float*)d_in[7];

    float* out = (float*)d_out;                       // [8,2048,128]
    float* att = out + (size_t)Bb*Mm*DOUT;            // [8,2048,2048]

    const int smem1 = (32*256 + 64*128) * 4;          // 65536
    const int smem2 = (16*2048 + 16*128 + 128*128)*4; // 204800

    cudaFuncSetAttribute(proj_kernel, cudaFuncAttributeMaxDynamicSharedMemorySize, smem1);
    cudaFuncSetAttribute(attn_kernel, cudaFuncAttributeMaxDynamicSharedMemorySize, smem2);

    proj_kernel<<<(Bb*Mm)/32, 128, smem1>>>(Y, idx, Wq, bq, Wk, bk, Wv, bv);
    attn_kernel<<<dim3(Mm/16, Bb), 256, smem2>>>(out, att);
}